// round 1
// baseline (speedup 1.0000x reference)
#include <cuda_runtime.h>
#include <cstdint>

#define HW     65536
#define BHW    131072
#define WDIM   1024
#define HDIM   64

// ---------------- global scratch (no cudaMalloc allowed) ----------------
// g_acc layout: [0]=N1(msel count) [1]=N0(mp0 count)
//   [2..9] S1  [10..17] Q1  [18..25] SG1  [26..33] QG1
//   [34..41] SG2 [42..49] QG2
//   [50..177] interleaved SA/QA: [50+2c]=SA_c [50+2c+1]=QA_c
__device__ float g_acc[178];
// g_ab layout: a1[0..7] b1[8..15] ag1[16..23] bg1[24..31]
//              ag2[32..39] bg2[40..47] aa[48..111] ba[112..175]
__device__ float g_ab[176];
__device__ float g_wts[9 * BHW];   // softmax weights, plane-major: [k][b*HW+p]

// ---------------- packed f32x2 accumulate: acc[0..31] += ci * wrow[0..63] ----------------
__device__ __forceinline__ void accum64(unsigned long long* acc, float ci, const float* wrow) {
    unsigned long long cc;
    unsigned ui = __float_as_uint(ci);
    asm("mov.b64 %0, {%1, %1};" : "=l"(cc) : "r"(ui));
    const ulonglong2* wp = reinterpret_cast<const ulonglong2*>(wrow);
#pragma unroll
    for (int t = 0; t < 16; t++) {
        ulonglong2 wv = wp[t];
        asm("fma.rn.f32x2 %0, %1, %2, %0;" : "+l"(acc[2 * t])     : "l"(cc), "l"(wv.x));
        asm("fma.rn.f32x2 %0, %1, %2, %0;" : "+l"(acc[2 * t + 1]) : "l"(cc), "l"(wv.y));
    }
}

// ---------------- block reduction -> atomicAdd into g_acc ----------------
template <int NV, int NW>
__device__ __forceinline__ void block_reduce_atomic(const float* vals, float* red, int tid, int accBase) {
    int lane = tid & 31, w = tid >> 5;
#pragma unroll
    for (int v = 0; v < NV; v++) {
        float r = vals[v];
#pragma unroll
        for (int o = 16; o; o >>= 1) r += __shfl_down_sync(0xffffffffu, r, o);
        if (lane == 0) red[v * NW + w] = r;
    }
    __syncthreads();
    if (tid < NV) {
        float r = 0.f;
#pragma unroll
        for (int ww = 0; ww < NW; ww++) r += red[tid * NW + ww];
        atomicAdd(&g_acc[accBase + tid], r);
    }
}

// ---------------- K0: zero accumulators ----------------
__global__ void k0_zero() {
    int t = threadIdx.x;
    if (t < 178) g_acc[t] = 0.f;
}

// ---------------- generic BN finalize: y = a*x + b ----------------
__global__ void fin_kernel(const float* __restrict__ gamma, const float* __restrict__ beta,
                           int C, int sOff, int qOff, int stride, int nOff, int abOff) {
    int c = threadIdx.x;
    if (c >= C) return;
    float n    = fmaxf(g_acc[nOff], 1.f);
    float mean = g_acc[sOff + c * stride] / n;
    float var  = g_acc[qOff + c * stride] / n - mean * mean;
    float a    = gamma[c] * rsqrtf(var + 1e-5f);
    g_ab[abOff + c]     = a;
    g_ab[abOff + C + c] = beta[c] - mean * a;
}

// ---------------- K1: stats for bn1 (pn@w1) and gbn1 (pn@g1) + mask counts ----------------
__global__ void k1_stats(const float* __restrict__ x, const float* __restrict__ mask,
                         const float* __restrict__ w1, const float* __restrict__ g1) {
    __shared__ float w1s[32], g1s[32];
    __shared__ float red[34 * 8];
    int tid = threadIdx.x;
    if (tid < 32) { w1s[tid] = w1[tid]; g1s[tid] = g1[tid]; }
    __syncthreads();

    int i = blockIdx.x * 256 + tid;
    int b = i >> 16, p = i & (HW - 1);
    int y = p >> 10, xc = p & (WDIM - 1);
    const float* xb = x + (size_t)b * 68 * HW + p;
    const float* mb = mask + (size_t)b * HW;

    float c0 = xb[0], c1 = xb[HW], c2 = xb[2 * HW], c3 = xb[3 * HW];
    float cnt1 = 0.f, cnt0 = (mb[p] > 0.f) ? 1.f : 0.f;
    float s1[8], q1[8], sg[8], qg[8];
#pragma unroll
    for (int j = 0; j < 8; j++) { s1[j] = q1[j] = sg[j] = qg[j] = 0.f; }

#pragma unroll
    for (int k = 0; k < 9; k++) {
        int dy = k / 3 - 1, dx = k % 3 - 1;
        int yy = y + dy, xx = xc + dx;
        if (yy < 0 || yy > HDIM - 1 || xx < 0 || xx > WDIM - 1) continue;
        int off = dy * WDIM + dx;
        if (!(mb[p + off] > 0.f)) continue;
        cnt1 += 1.f;
        float pn0 = xb[off] - c0, pn1 = xb[HW + off] - c1;
        float pn2 = xb[2 * HW + off] - c2, pn3 = xb[3 * HW + off] - c3;
#pragma unroll
        for (int j = 0; j < 8; j++) {
            float h = pn0 * w1s[j * 4] + pn1 * w1s[j * 4 + 1] + pn2 * w1s[j * 4 + 2] + pn3 * w1s[j * 4 + 3];
            s1[j] += h; q1[j] += h * h;
            float qv = pn0 * g1s[j * 4] + pn1 * g1s[j * 4 + 1] + pn2 * g1s[j * 4 + 2] + pn3 * g1s[j * 4 + 3];
            sg[j] += qv; qg[j] += qv * qv;
        }
    }

    float vals[34];
    vals[0] = cnt1; vals[1] = cnt0;
#pragma unroll
    for (int j = 0; j < 8; j++) {
        vals[2 + j] = s1[j]; vals[10 + j] = q1[j];
        vals[18 + j] = sg[j]; vals[26 + j] = qg[j];
    }
    block_reduce_atomic<34, 8>(vals, red, tid, 0);
}

// ---------------- K2: softmax weights + gbn2 input stats ----------------
__global__ void k2_wts(const float* __restrict__ x, const float* __restrict__ mask,
                       const float* __restrict__ w1, const float* __restrict__ w2,
                       const float* __restrict__ b2, const float* __restrict__ g1,
                       const float* __restrict__ g2) {
    __shared__ float w1s[32], g1s[32], g2s[64], w2s[8], abp[32];
    __shared__ float b2s;
    __shared__ float red[16 * 8];
    int tid = threadIdx.x;
    if (tid < 32) { w1s[tid] = w1[tid]; g1s[tid] = g1[tid]; abp[tid] = g_ab[tid]; }
    if (tid < 64) g2s[tid] = g2[tid];
    if (tid < 8)  w2s[tid] = w2[tid];
    if (tid == 0) b2s = b2[0];
    __syncthreads();

    int i = blockIdx.x * 256 + tid;
    int b = i >> 16, p = i & (HW - 1);
    int y = p >> 10, xc = p & (WDIM - 1);
    const float* xb = x + (size_t)b * 68 * HW + p;
    const float* mb = mask + (size_t)b * HW;

    float c0 = xb[0], c1 = xb[HW], c2 = xb[2 * HW], c3 = xb[3 * HW];
    float logit[9];
    float sg2[8], qg2[8];
#pragma unroll
    for (int j = 0; j < 8; j++) { sg2[j] = qg2[j] = 0.f; }

#pragma unroll
    for (int k = 0; k < 9; k++) {
        int dy = k / 3 - 1, dx = k % 3 - 1;
        int yy = y + dy, xx = xc + dx;
        float lg = 0.f;
        if (yy >= 0 && yy < HDIM && xx >= 0 && xx < WDIM) {
            int off = dy * WDIM + dx;
            if (mb[p + off] > 0.f) {
                float pn0 = xb[off] - c0, pn1 = xb[HW + off] - c1;
                float pn2 = xb[2 * HW + off] - c2, pn3 = xb[3 * HW + off] - c3;
                float u[8];
                float l = b2s;
#pragma unroll
                for (int j = 0; j < 8; j++) {
                    float h = pn0 * w1s[j * 4] + pn1 * w1s[j * 4 + 1] + pn2 * w1s[j * 4 + 2] + pn3 * w1s[j * 4 + 3];
                    float hn = fmaxf(h * abp[j] + abp[8 + j], 0.f);
                    l += hn * w2s[j];
                    float qv = pn0 * g1s[j * 4] + pn1 * g1s[j * 4 + 1] + pn2 * g1s[j * 4 + 2] + pn3 * g1s[j * 4 + 3];
                    u[j] = fmaxf(qv * abp[16 + j] + abp[24 + j], 0.f);
                }
                lg = l;
#pragma unroll
                for (int j = 0; j < 8; j++) {
                    float vv = 0.f;
#pragma unroll
                    for (int m = 0; m < 8; m++) vv += u[m] * g2s[j * 8 + m];
                    sg2[j] += vv; qg2[j] += vv * vv;
                }
            }
        }
        logit[k] = lg;
    }

    float mx = logit[0];
#pragma unroll
    for (int k = 1; k < 9; k++) mx = fmaxf(mx, logit[k]);
    float s = 0.f, e[9];
#pragma unroll
    for (int k = 0; k < 9; k++) { e[k] = __expf(logit[k] - mx); s += e[k]; }
    float inv = 1.f / s;
#pragma unroll
    for (int k = 0; k < 9; k++) g_wts[(size_t)k * BHW + i] = e[k] * inv;

    float vals[16];
#pragma unroll
    for (int j = 0; j < 8; j++) { vals[j] = sg2[j]; vals[8 + j] = qg2[j]; }
    block_reduce_atomic<16, 8>(vals, red, tid, 34);
}

// ---------------- K3: fagg + g path + w_agg GEMM + abn stats ----------------
__global__ void __launch_bounds__(128) k3_main(const float* __restrict__ x, const float* __restrict__ mask,
                                               const float* __restrict__ g1, const float* __restrict__ g2,
                                               const float* __restrict__ w_agg, float* __restrict__ out) {
    // wTs[i][o] = w_agg[o][i], row stride 68 floats (272B: 16B aligned, conflict-spread)
    __shared__ __align__(16) float wTs[136 * 68];
    __shared__ float g1s[32], g2s[64], prm[32];
    __shared__ float red[128 * 4];
    int tid = threadIdx.x;

    for (int e = tid; e < 64 * 136; e += 128) {
        float v = w_agg[e];               // coalesced read
        int o = e / 136, ii = e - o * 136;
        wTs[ii * 68 + o] = v;             // transposed store
    }
    if (tid < 32) { g1s[tid] = g1[tid]; prm[tid] = g_ab[16 + tid]; }
    if (tid < 64) g2s[tid] = g2[tid];
    __syncthreads();

    int i = blockIdx.x * 128 + tid;
    int b = i >> 16, p = i & (HW - 1);
    int y = p >> 10, xc = p & (WDIM - 1);
    const float* xb = x + (size_t)b * 68 * HW + p;
    const float* mb = mask + (size_t)b * HW;

    float wv[9];
#pragma unroll
    for (int k = 0; k < 9; k++) wv[k] = g_wts[(size_t)k * BHW + i];

    unsigned msel = 0, vmask = 0;
#pragma unroll
    for (int k = 0; k < 9; k++) {
        int dy = k / 3 - 1, dx = k % 3 - 1;
        int yy = y + dy, xx = xc + dx;
        if (yy >= 0 && yy < HDIM && xx >= 0 && xx < WDIM) {
            vmask |= 1u << k;
            if (mb[p + dy * WDIM + dx] > 0.f) msel |= 1u << k;
        }
    }

    float c0 = xb[0], c1 = xb[HW], c2 = xb[2 * HW], c3 = xb[3 * HW];

    unsigned long long acc[32];
#pragma unroll
    for (int t = 0; t < 32; t++) acc[t] = 0ULL;

    // ---- g path: relu(bn(pn@g1)) @ g2 -> relu(bn) -> *wts -> 72 concat entries ----
#pragma unroll
    for (int k = 0; k < 9; k++) {
        if ((msel >> k) & 1u) {
            const int off = (k / 3 - 1) * WDIM + (k % 3 - 1);
            float pn0 = xb[off] - c0, pn1 = xb[HW + off] - c1;
            float pn2 = xb[2 * HW + off] - c2, pn3 = xb[3 * HW + off] - c3;
            float u[8];
#pragma unroll
            for (int j = 0; j < 8; j++) {
                float qv = pn0 * g1s[j * 4] + pn1 * g1s[j * 4 + 1] + pn2 * g1s[j * 4 + 2] + pn3 * g1s[j * 4 + 3];
                u[j] = fmaxf(qv * prm[j] + prm[8 + j], 0.f);
            }
#pragma unroll
            for (int j = 0; j < 8; j++) {
                float vvv = 0.f;
#pragma unroll
                for (int m = 0; m < 8; m++) vvv += u[m] * g2s[j * 8 + m];
                float gv = fmaxf(vvv * prm[16 + j] + prm[24 + j], 0.f) * wv[k];
                accum64(acc, gv, &wTs[(64 + k * 8 + j) * 68]);
            }
        }
    }

    // ---- fagg: per feature channel, 9-neighbor weighted sum, fold into out ----
#pragma unroll 2
    for (int c = 0; c < 64; c++) {
        const float* xch = xb + (size_t)(4 + c) * HW;
        float fc = 0.f;
#pragma unroll
        for (int k = 0; k < 9; k++) {
            if ((vmask >> k) & 1u) {
                const int off = (k / 3 - 1) * WDIM + (k % 3 - 1);
                fc += wv[k] * xch[off];
            }
        }
        accum64(acc, fc, &wTs[c * 68]);
    }

    // ---- unpack, write raw out (coalesced per channel), abn stats ----
    float ov[64];
#pragma unroll
    for (int t = 0; t < 32; t++) {
        ov[2 * t]     = __uint_as_float((unsigned)(acc[t]));
        ov[2 * t + 1] = __uint_as_float((unsigned)(acc[t] >> 32));
    }
    float* ob = out + (size_t)b * 64 * HW + p;
#pragma unroll 8
    for (int o = 0; o < 64; o++) ob[(size_t)o * HW] = ov[o];

    bool mp0 = (msel >> 4) & 1u;
    int lane = tid & 31, w = tid >> 5;
#pragma unroll
    for (int o = 0; o < 64; o++) {
        float r = mp0 ? ov[o] : 0.f;
        float r2 = r * r;
#pragma unroll
        for (int s = 16; s; s >>= 1) {
            r  += __shfl_down_sync(0xffffffffu, r, s);
            r2 += __shfl_down_sync(0xffffffffu, r2, s);
        }
        if (lane == 0) { red[(2 * o) * 4 + w] = r; red[(2 * o + 1) * 4 + w] = r2; }
    }
    __syncthreads();
    if (tid < 128) {
        float r = red[tid * 4] + red[tid * 4 + 1] + red[tid * 4 + 2] + red[tid * 4 + 3];
        atomicAdd(&g_acc[50 + tid], r);
    }
}

// ---------------- K4: in-place abn normalize + relu + mask ----------------
__global__ void k4_final(float* __restrict__ out, const float* __restrict__ mask) {
    int t = blockIdx.x * 256 + threadIdx.x;   // float4 index; grid covers exactly
    int e = t * 4;
    int b = e >> 22;
    int c = (e >> 16) & 63;
    int p = e & (HW - 1);
    float a  = g_ab[48 + c];
    float bb = g_ab[112 + c];
    float4 v  = reinterpret_cast<float4*>(out)[t];
    float4 mk = *reinterpret_cast<const float4*>(mask + (size_t)b * HW + p);
    v.x = (mk.x > 0.f) ? fmaxf(v.x * a + bb, 0.f) : 0.f;
    v.y = (mk.y > 0.f) ? fmaxf(v.y * a + bb, 0.f) : 0.f;
    v.z = (mk.z > 0.f) ? fmaxf(v.z * a + bb, 0.f) : 0.f;
    v.w = (mk.w > 0.f) ? fmaxf(v.w * a + bb, 0.f) : 0.f;
    reinterpret_cast<float4*>(out)[t] = v;
}

// ---------------- host launcher ----------------
extern "C" void kernel_launch(void* const* d_in, const int* in_sizes, int n_in,
                              void* d_out, int out_size) {
    const float* x      = (const float*)d_in[0];
    const float* mask   = (const float*)d_in[1];
    const float* w1     = (const float*)d_in[2];
    const float* bn1_g  = (const float*)d_in[3];
    const float* bn1_b  = (const float*)d_in[4];
    const float* w2     = (const float*)d_in[5];
    const float* b2     = (const float*)d_in[6];
    const float* g1     = (const float*)d_in[7];
    const float* gbn1_g = (const float*)d_in[8];
    const float* gbn1_b = (const float*)d_in[9];
    const float* g2     = (const float*)d_in[10];
    const float* gbn2_g = (const float*)d_in[11];
    const float* gbn2_b = (const float*)d_in[12];
    const float* w_agg  = (const float*)d_in[13];
    const float* abn_g  = (const float*)d_in[14];
    const float* abn_b  = (const float*)d_in[15];
    float* out = (float*)d_out;

    k0_zero<<<1, 256>>>();
    k1_stats<<<BHW / 256, 256>>>(x, mask, w1, g1);
    fin_kernel<<<1, 64>>>(bn1_g, bn1_b, 8, 2, 10, 1, 0, 0);     // bn1  -> a1/b1
    fin_kernel<<<1, 64>>>(gbn1_g, gbn1_b, 8, 18, 26, 1, 0, 16); // gbn1 -> ag1/bg1
    k2_wts<<<BHW / 256, 256>>>(x, mask, w1, w2, b2, g1, g2);
    fin_kernel<<<1, 64>>>(gbn2_g, gbn2_b, 8, 34, 42, 1, 0, 32); // gbn2 -> ag2/bg2
    k3_main<<<BHW / 128, 128>>>(x, mask, g1, g2, w_agg, out);
    fin_kernel<<<1, 64>>>(abn_g, abn_b, 64, 50, 51, 2, 1, 48);  // abn  -> aa/ba
    k4_final<<<(2 * 64 * HW / 4) / 256, 256>>>(out, mask);
}

// round 2
// speedup vs baseline: 1.1891x; 1.1891x over previous
#include <cuda_runtime.h>
#include <cstdint>

#define HW     65536
#define BHW    131072
#define WDIM   1024
#define HDIM   64

// ---------------- global scratch (no cudaMalloc allowed) ----------------
// g_acc layout:
// [0]=N1 (masked (p,k) count)  [1]=N0 (mp0 count)
// [2..5]   Sum pn_a                  (4)
// [6..15]  Sum pn_a*pn_b, a<=b       (10)  order: 00,01,02,03,11,12,13,22,23,33
// [16..23] SG2   [24..31] QG2        (gbn2 input stats)
// [32..159] interleaved: [32+2c]=SA_c [33+2c]=QA_c  (abn stats, 64 ch)
__device__ float g_acc[160];
// g_ab layout: a1[0..7] b1[8..15] ag1[16..23] bg1[24..31]
//              ag2[32..39] bg2[40..47] aa[48..111] ba[112..175]
__device__ float g_ab[176];
__device__ float g_wts[9 * BHW];   // softmax weights, plane-major: [k][b*HW+p]

// ---------------- packed f32x2 accumulate: acc[0..31] += ci * wrow[0..63] ----------------
__device__ __forceinline__ void accum64(unsigned long long* acc, float ci, const float* wrow) {
    unsigned long long cc;
    unsigned ui = __float_as_uint(ci);
    asm("mov.b64 %0, {%1, %1};" : "=l"(cc) : "r"(ui));
    const ulonglong2* wp = reinterpret_cast<const ulonglong2*>(wrow);
#pragma unroll
    for (int t = 0; t < 16; t++) {
        ulonglong2 wv = wp[t];
        asm("fma.rn.f32x2 %0, %1, %2, %0;" : "+l"(acc[2 * t])     : "l"(cc), "l"(wv.x));
        asm("fma.rn.f32x2 %0, %1, %2, %0;" : "+l"(acc[2 * t + 1]) : "l"(cc), "l"(wv.y));
    }
}

// ---------------- block reduction -> atomicAdd into g_acc ----------------
template <int NV, int NW>
__device__ __forceinline__ void block_reduce_atomic(const float* vals, float* red, int tid, int accBase) {
    int lane = tid & 31, w = tid >> 5;
#pragma unroll
    for (int v = 0; v < NV; v++) {
        float r = vals[v];
#pragma unroll
        for (int o = 16; o; o >>= 1) r += __shfl_down_sync(0xffffffffu, r, o);
        if (lane == 0) red[v * NW + w] = r;
    }
    __syncthreads();
    if (tid < NV) {
        float r = 0.f;
#pragma unroll
        for (int ww = 0; ww < NW; ww++) r += red[tid * NW + ww];
        atomicAdd(&g_acc[accBase + tid], r);
    }
}

// ---------------- K0: zero accumulators ----------------
__global__ void k0_zero() {
    int t = threadIdx.x;
    if (t < 160) g_acc[t] = 0.f;
}

// ---------------- K1: pn moment stats + mask counts ----------------
__global__ void k1_stats(const float* __restrict__ x, const float* __restrict__ mask) {
    __shared__ float red[16 * 8];
    int tid = threadIdx.x;

    int i = blockIdx.x * 256 + tid;
    int b = i >> 16, p = i & (HW - 1);
    int y = p >> 10, xc = p & (WDIM - 1);
    const float* xb = x + (size_t)b * 68 * HW + p;
    const float* mb = mask + (size_t)b * HW;

    float c0 = xb[0], c1 = xb[HW], c2 = xb[2 * HW], c3 = xb[3 * HW];
    float cnt1 = 0.f, cnt0 = (mb[p] > 0.f) ? 1.f : 0.f;
    float s[4] = {0.f, 0.f, 0.f, 0.f};
    float q[10];
#pragma unroll
    for (int j = 0; j < 10; j++) q[j] = 0.f;

#pragma unroll
    for (int k = 0; k < 9; k++) {
        int dy = k / 3 - 1, dx = k % 3 - 1;
        int yy = y + dy, xx = xc + dx;
        if (yy < 0 || yy > HDIM - 1 || xx < 0 || xx > WDIM - 1) continue;
        int off = dy * WDIM + dx;
        if (!(mb[p + off] > 0.f)) continue;
        cnt1 += 1.f;
        float pn0 = xb[off] - c0, pn1 = xb[HW + off] - c1;
        float pn2 = xb[2 * HW + off] - c2, pn3 = xb[3 * HW + off] - c3;
        s[0] += pn0; s[1] += pn1; s[2] += pn2; s[3] += pn3;
        q[0] += pn0 * pn0; q[1] += pn0 * pn1; q[2] += pn0 * pn2; q[3] += pn0 * pn3;
        q[4] += pn1 * pn1; q[5] += pn1 * pn2; q[6] += pn1 * pn3;
        q[7] += pn2 * pn2; q[8] += pn2 * pn3; q[9] += pn3 * pn3;
    }

    float vals[16];
    vals[0] = cnt1; vals[1] = cnt0;
#pragma unroll
    for (int a = 0; a < 4; a++) vals[2 + a] = s[a];
#pragma unroll
    for (int j = 0; j < 10; j++) vals[6 + j] = q[j];
    block_reduce_atomic<16, 8>(vals, red, tid, 0);
}

// ---------------- finA: derive bn1 + gbn1 scale/shift from pn moments ----------------
__global__ void finA_kernel(const float* __restrict__ w1, const float* __restrict__ g1,
                            const float* __restrict__ bn1_g, const float* __restrict__ bn1_b,
                            const float* __restrict__ gbn1_g, const float* __restrict__ gbn1_b) {
    int tid = threadIdx.x;
    if (tid >= 16) return;
    int path = tid >> 3, j = tid & 7;
    const float* wrow = (path ? g1 : w1) + j * 4;
    float n = fmaxf(g_acc[0], 1.f);
    float m[4], w[4];
#pragma unroll
    for (int a = 0; a < 4; a++) { m[a] = g_acc[2 + a] / n; w[a] = wrow[a]; }
    // E[(w.pn)^2] = w^T (Q/n) w  using symmetric packed Q
    const int qi[4][4] = {{0,1,2,3},{1,4,5,6},{2,5,7,8},{3,6,8,9}};
    float e2 = 0.f, mean = 0.f;
#pragma unroll
    for (int a = 0; a < 4; a++) {
        mean += w[a] * m[a];
        float row = 0.f;
#pragma unroll
        for (int bb = 0; bb < 4; bb++) row += w[bb] * (g_acc[6 + qi[a][bb]] / n);
        e2 += w[a] * row;
    }
    float var = e2 - mean * mean;
    float gam = path ? gbn1_g[j] : bn1_g[j];
    float bet = path ? gbn1_b[j] : bn1_b[j];
    float a_ = gam * rsqrtf(var + 1e-5f);
    int base = path ? 16 : 0;
    g_ab[base + j]     = a_;
    g_ab[base + 8 + j] = bet - mean * a_;
}

// ---------------- generic BN finalize: y = a*x + b ----------------
__global__ void fin_kernel(const float* __restrict__ gamma, const float* __restrict__ beta,
                           int C, int sOff, int qOff, int stride, int nOff, int abOff) {
    int c = threadIdx.x;
    if (c >= C) return;
    float n    = fmaxf(g_acc[nOff], 1.f);
    float mean = g_acc[sOff + c * stride] / n;
    float var  = g_acc[qOff + c * stride] / n - mean * mean;
    float a    = gamma[c] * rsqrtf(var + 1e-5f);
    g_ab[abOff + c]     = a;
    g_ab[abOff + C + c] = beta[c] - mean * a;
}

// ---------------- K2: softmax weights + gbn2 input stats ----------------
__global__ void k2_wts(const float* __restrict__ x, const float* __restrict__ mask,
                       const float* __restrict__ w1, const float* __restrict__ w2,
                       const float* __restrict__ b2, const float* __restrict__ g1,
                       const float* __restrict__ g2) {
    __shared__ float w1s[32], g1s[32], g2s[64], w2s[8], abp[32];
    __shared__ float b2s;
    __shared__ float red[16 * 8];
    int tid = threadIdx.x;
    if (tid < 32) { w1s[tid] = w1[tid]; g1s[tid] = g1[tid]; abp[tid] = g_ab[tid]; }
    if (tid < 64) g2s[tid] = g2[tid];
    if (tid < 8)  w2s[tid] = w2[tid];
    if (tid == 0) b2s = b2[0];
    __syncthreads();

    int i = blockIdx.x * 256 + tid;
    int b = i >> 16, p = i & (HW - 1);
    int y = p >> 10, xc = p & (WDIM - 1);
    const float* xb = x + (size_t)b * 68 * HW + p;
    const float* mb = mask + (size_t)b * HW;

    float c0 = xb[0], c1 = xb[HW], c2 = xb[2 * HW], c3 = xb[3 * HW];
    float logit[9];
    float sg2[8], qg2[8];
#pragma unroll
    for (int j = 0; j < 8; j++) { sg2[j] = qg2[j] = 0.f; }

#pragma unroll
    for (int k = 0; k < 9; k++) {
        int dy = k / 3 - 1, dx = k % 3 - 1;
        int yy = y + dy, xx = xc + dx;
        float lg = 0.f;
        if (yy >= 0 && yy < HDIM && xx >= 0 && xx < WDIM) {
            int off = dy * WDIM + dx;
            if (mb[p + off] > 0.f) {
                float pn0 = xb[off] - c0, pn1 = xb[HW + off] - c1;
                float pn2 = xb[2 * HW + off] - c2, pn3 = xb[3 * HW + off] - c3;
                float u[8];
                float l = b2s;
#pragma unroll
                for (int j = 0; j < 8; j++) {
                    float h = pn0 * w1s[j * 4] + pn1 * w1s[j * 4 + 1] + pn2 * w1s[j * 4 + 2] + pn3 * w1s[j * 4 + 3];
                    float hn = fmaxf(h * abp[j] + abp[8 + j], 0.f);
                    l += hn * w2s[j];
                    float qv = pn0 * g1s[j * 4] + pn1 * g1s[j * 4 + 1] + pn2 * g1s[j * 4 + 2] + pn3 * g1s[j * 4 + 3];
                    u[j] = fmaxf(qv * abp[16 + j] + abp[24 + j], 0.f);
                }
                lg = l;
#pragma unroll
                for (int j = 0; j < 8; j++) {
                    float vv = 0.f;
#pragma unroll
                    for (int m = 0; m < 8; m++) vv += u[m] * g2s[j * 8 + m];
                    sg2[j] += vv; qg2[j] += vv * vv;
                }
            }
        }
        logit[k] = lg;
    }

    float mx = logit[0];
#pragma unroll
    for (int k = 1; k < 9; k++) mx = fmaxf(mx, logit[k]);
    float s = 0.f, e[9];
#pragma unroll
    for (int k = 0; k < 9; k++) { e[k] = __expf(logit[k] - mx); s += e[k]; }
    float inv = 1.f / s;
#pragma unroll
    for (int k = 0; k < 9; k++) g_wts[(size_t)k * BHW + i] = e[k] * inv;

    float vals[16];
#pragma unroll
    for (int j = 0; j < 8; j++) { vals[j] = sg2[j]; vals[8 + j] = qg2[j]; }
    block_reduce_atomic<16, 8>(vals, red, tid, 16);
}

// ---------------- K3: fagg + g path + w_agg GEMM + abn stats ----------------
__global__ void __launch_bounds__(128) k3_main(const float* __restrict__ x, const float* __restrict__ mask,
                                               const float* __restrict__ g1, const float* __restrict__ g2,
                                               const float* __restrict__ w_agg, float* __restrict__ out) {
    // wTs[i][o] = w_agg[o][i], row stride 64 (reads are warp-uniform broadcasts)
    __shared__ __align__(16) float wTs[136 * 64];
    __shared__ float g1s[32], g2s[64], prm[32];
    __shared__ float red[128 * 4];
    int tid = threadIdx.x;

    for (int e = tid; e < 64 * 136; e += 128) {
        float v = w_agg[e];               // coalesced read
        int o = e / 136, ii = e - o * 136;
        wTs[ii * 64 + o] = v;             // transposed store
    }
    if (tid < 32) { g1s[tid] = g1[tid]; prm[tid] = g_ab[16 + tid]; }
    if (tid < 64) g2s[tid] = g2[tid];
    __syncthreads();

    int i = blockIdx.x * 128 + tid;
    int b = i >> 16, p = i & (HW - 1);
    int y = p >> 10, xc = p & (WDIM - 1);
    const float* xb = x + (size_t)b * 68 * HW + p;
    const float* mb = mask + (size_t)b * HW;

    float wv[9];
#pragma unroll
    for (int k = 0; k < 9; k++) wv[k] = g_wts[(size_t)k * BHW + i];

    unsigned msel = 0, vmask = 0;
#pragma unroll
    for (int k = 0; k < 9; k++) {
        int dy = k / 3 - 1, dx = k % 3 - 1;
        int yy = y + dy, xx = xc + dx;
        if (yy >= 0 && yy < HDIM && xx >= 0 && xx < WDIM) {
            vmask |= 1u << k;
            if (mb[p + dy * WDIM + dx] > 0.f) msel |= 1u << k;
        }
    }

    float c0 = xb[0], c1 = xb[HW], c2 = xb[2 * HW], c3 = xb[3 * HW];

    unsigned long long acc[32];
#pragma unroll
    for (int t = 0; t < 32; t++) acc[t] = 0ULL;

    // ---- g path: relu(bn(pn@g1)) @ g2 -> relu(bn) -> *wts -> 72 concat entries ----
#pragma unroll
    for (int k = 0; k < 9; k++) {
        if ((msel >> k) & 1u) {
            const int off = (k / 3 - 1) * WDIM + (k % 3 - 1);
            float pn0 = xb[off] - c0, pn1 = xb[HW + off] - c1;
            float pn2 = xb[2 * HW + off] - c2, pn3 = xb[3 * HW + off] - c3;
            float u[8];
#pragma unroll
            for (int j = 0; j < 8; j++) {
                float qv = pn0 * g1s[j * 4] + pn1 * g1s[j * 4 + 1] + pn2 * g1s[j * 4 + 2] + pn3 * g1s[j * 4 + 3];
                u[j] = fmaxf(qv * prm[j] + prm[8 + j], 0.f);
            }
#pragma unroll
            for (int j = 0; j < 8; j++) {
                float vvv = 0.f;
#pragma unroll
                for (int m = 0; m < 8; m++) vvv += u[m] * g2s[j * 8 + m];
                float gv = fmaxf(vvv * prm[16 + j] + prm[24 + j], 0.f) * wv[k];
                accum64(acc, gv, &wTs[(64 + k * 8 + j) * 64]);
            }
        }
    }

    // ---- fagg: per feature channel, 9-neighbor weighted sum, fold into out ----
#pragma unroll 2
    for (int c = 0; c < 64; c++) {
        const float* xch = xb + (size_t)(4 + c) * HW;
        float fc = 0.f;
#pragma unroll
        for (int k = 0; k < 9; k++) {
            if ((vmask >> k) & 1u) {
                const int off = (k / 3 - 1) * WDIM + (k % 3 - 1);
                fc += wv[k] * xch[off];
            }
        }
        accum64(acc, fc, &wTs[c * 64]);
    }

    // ---- fused: unpack + store + abn stats, no ov[64] array ----
    float* ob = out + (size_t)b * 64 * HW + p;
    bool mp0 = (msel >> 4) & 1u;
    int lane = tid & 31, w = tid >> 5;
#pragma unroll
    for (int t = 0; t < 32; t++) {
        float v0 = __uint_as_float((unsigned)(acc[t]));
        float v1 = __uint_as_float((unsigned)(acc[t] >> 32));
        ob[(size_t)(2 * t) * HW]     = v0;
        ob[(size_t)(2 * t + 1) * HW] = v1;
        float r0 = mp0 ? v0 : 0.f, r1 = mp0 ? v1 : 0.f;
        float q0 = r0 * r0, q1 = r1 * r1;
#pragma unroll
        for (int s = 16; s; s >>= 1) {
            r0 += __shfl_down_sync(0xffffffffu, r0, s);
            q0 += __shfl_down_sync(0xffffffffu, q0, s);
            r1 += __shfl_down_sync(0xffffffffu, r1, s);
            q1 += __shfl_down_sync(0xffffffffu, q1, s);
        }
        if (lane == 0) {
            red[(4 * t + 0) * 4 + w] = r0;
            red[(4 * t + 1) * 4 + w] = q0;
            red[(4 * t + 2) * 4 + w] = r1;
            red[(4 * t + 3) * 4 + w] = q1;
        }
    }
    __syncthreads();
    // red row r maps exactly to g_acc[32 + r]  (S_c at 32+2c, Q_c at 33+2c)
    if (tid < 128) {
        float r = red[tid * 4] + red[tid * 4 + 1] + red[tid * 4 + 2] + red[tid * 4 + 3];
        atomicAdd(&g_acc[32 + tid], r);
    }
}

// ---------------- K4: in-place abn normalize + relu + mask ----------------
__global__ void k4_final(float* __restrict__ out, const float* __restrict__ mask) {
    int t = blockIdx.x * 256 + threadIdx.x;   // float4 index; grid covers exactly
    int e = t * 4;
    int b = e >> 22;
    int c = (e >> 16) & 63;
    int p = e & (HW - 1);
    float a  = g_ab[48 + c];
    float bb = g_ab[112 + c];
    float4 v  = reinterpret_cast<float4*>(out)[t];
    float4 mk = *reinterpret_cast<const float4*>(mask + (size_t)b * HW + p);
    v.x = (mk.x > 0.f) ? fmaxf(v.x * a + bb, 0.f) : 0.f;
    v.y = (mk.y > 0.f) ? fmaxf(v.y * a + bb, 0.f) : 0.f;
    v.z = (mk.z > 0.f) ? fmaxf(v.z * a + bb, 0.f) : 0.f;
    v.w = (mk.w > 0.f) ? fmaxf(v.w * a + bb, 0.f) : 0.f;
    reinterpret_cast<float4*>(out)[t] = v;
}

// ---------------- host launcher ----------------
extern "C" void kernel_launch(void* const* d_in, const int* in_sizes, int n_in,
                              void* d_out, int out_size) {
    const float* x      = (const float*)d_in[0];
    const float* mask   = (const float*)d_in[1];
    const float* w1     = (const float*)d_in[2];
    const float* bn1_g  = (const float*)d_in[3];
    const float* bn1_b  = (const float*)d_in[4];
    const float* w2     = (const float*)d_in[5];
    const float* b2     = (const float*)d_in[6];
    const float* g1     = (const float*)d_in[7];
    const float* gbn1_g = (const float*)d_in[8];
    const float* gbn1_b = (const float*)d_in[9];
    const float* g2     = (const float*)d_in[10];
    const float* gbn2_g = (const float*)d_in[11];
    const float* gbn2_b = (const float*)d_in[12];
    const float* w_agg  = (const float*)d_in[13];
    const float* abn_g  = (const float*)d_in[14];
    const float* abn_b  = (const float*)d_in[15];
    float* out = (float*)d_out;

    k0_zero<<<1, 256>>>();                                                  // launch 0
    k1_stats<<<BHW / 256, 256>>>(x, mask);                                  // launch 1
    finA_kernel<<<1, 32>>>(w1, g1, bn1_g, bn1_b, gbn1_g, gbn1_b);           // launch 2
    k2_wts<<<BHW / 256, 256>>>(x, mask, w1, w2, b2, g1, g2);                // launch 3
    fin_kernel<<<1, 64>>>(gbn2_g, gbn2_b, 8, 16, 24, 1, 0, 32);             // launch 4
    k3_main<<<BHW / 128, 128>>>(x, mask, g1, g2, w_agg, out);               // launch 5 <- profiled
    fin_kernel<<<1, 64>>>(abn_g, abn_b, 64, 32, 33, 2, 1, 48);              // launch 6
    k4_final<<<(2 * 64 * HW / 4) / 256, 256>>>(out, mask);                  // launch 7
}